// round 1
// baseline (speedup 1.0000x reference)
#include <cuda_runtime.h>

#define NUM_CITIES 50000
#define EMB 50
#define HID 64
#define G4 256          // 4 * HID
#define BATCH 1024
#define SEQ 512

// Scratch (no allocation allowed -> device globals)
__device__ float g_emb_proj[NUM_CITIES * G4];   // emb @ W_ih^T + (b_ih+b_hh), 51.2MB
__device__ float g_hfin[BATCH * HID];           // final hidden state

// ---------------------------------------------------------------------------
// helpers
// ---------------------------------------------------------------------------
__device__ __forceinline__ float2 ffma2(float2 a, float2 b, float2 c) {
    unsigned long long A = *reinterpret_cast<unsigned long long*>(&a);
    unsigned long long B = *reinterpret_cast<unsigned long long*>(&b);
    unsigned long long C = *reinterpret_cast<unsigned long long*>(&c);
    unsigned long long D;
    asm("fma.rn.f32x2 %0, %1, %2, %3;" : "=l"(D) : "l"(A), "l"(B), "l"(C));
    return *reinterpret_cast<float2*>(&D);
}

__device__ __forceinline__ float fast_ex2(float x) {
    float r; asm("ex2.approx.f32 %0, %1;" : "=f"(r) : "f"(x)); return r;
}
__device__ __forceinline__ float fast_rcp(float x) {
    float r; asm("rcp.approx.f32 %0, %1;" : "=f"(r) : "f"(x)); return r;
}
__device__ __forceinline__ float sigmoid_(float x) {
    return fast_rcp(1.0f + fast_ex2(-1.4426950408889634f * x));
}
__device__ __forceinline__ float tanh_(float x) {
    // tanh(x) = 2*sigmoid(2x) - 1
    return fmaf(2.0f, sigmoid_(2.0f * x), -1.0f);
}

// ---------------------------------------------------------------------------
// K1: emb_proj[r][j] = sum_k emb[r][k] * W_ih[j][k] + (b_ih[j]+b_hh[j])
// grid: 2500 CTAs x 256 threads, 20 rows per CTA, thread = output column j
// ---------------------------------------------------------------------------
__global__ void __launch_bounds__(256) k1_embproj(
    const float* __restrict__ emb, const float* __restrict__ W_ih,
    const float* __restrict__ b_ih, const float* __restrict__ b_hh)
{
    __shared__ float es[20][52];  // 52 = pad to multiple of 4 (float4 reads)
    const int j  = threadIdx.x;
    const int r0 = blockIdx.x * 20;

    float w[52];
#pragma unroll
    for (int k = 0; k < 50; k++) w[k] = W_ih[j * 50 + k];
    w[50] = 0.0f; w[51] = 0.0f;
    const float bias = b_ih[j] + b_hh[j];

    for (int idx = j; idx < 20 * 50; idx += 256)
        es[idx / 50][idx % 50] = emb[(r0 + idx / 50) * 50 + (idx % 50)];
    if (j < 40) es[j >> 1][50 + (j & 1)] = 0.0f;
    __syncthreads();

#pragma unroll 4
    for (int r = 0; r < 20; r++) {
        float acc = bias;
#pragma unroll
        for (int q = 0; q < 13; q++) {
            float4 e4 = *reinterpret_cast<const float4*>(&es[r][q * 4]);
            acc = fmaf(e4.x, w[4 * q + 0], acc);
            acc = fmaf(e4.y, w[4 * q + 1], acc);
            acc = fmaf(e4.z, w[4 * q + 2], acc);
            acc = fmaf(e4.w, w[4 * q + 3], acc);
        }
        g_emb_proj[(r0 + r) * G4 + j] = acc;
    }
}

// ---------------------------------------------------------------------------
// K2: LSTM recurrence. 128 CTAs x 256 threads, 8 batch rows per CTA.
// Thread j owns gate column j (W_hh row j in regs, packed by k-pairs for f32x2).
// Gate order: j in [0,64)=i, [64,128)=f, [128,192)=g(tanh), [192,256)=o
// ---------------------------------------------------------------------------
__global__ void __launch_bounds__(256) k2_lstm(
    const int* __restrict__ x, const float* __restrict__ W_hh)
{
    __shared__ float hS[8][64];    // h[b][k]
    __shared__ float gS[8][256];   // activated gates
    __shared__ int   xs[2][8];     // double-buffered token indices

    const int j  = threadIdx.x;
    const int b0 = blockIdx.x * 8;

    // W_hh row j, packed as float2 over k-pairs
    float2 wk[32];
    {
        const float2* wr = reinterpret_cast<const float2*>(W_hh + j * HID);
#pragma unroll
        for (int q = 0; q < 32; q++) wk[q] = wr[q];
    }

    // zero h (512 entries / 256 threads)
    hS[j >> 5][(j & 31)]      = 0.0f;
    hS[j >> 5][(j & 31) + 32] = 0.0f;
    if (j < 8) xs[0][j] = x[(b0 + j) * SEQ];

    const int ku = j & 63;   // update-phase h column
    const int pu = j >> 6;   // update-phase batch pair (0..3)
    float2 c     = make_float2(0.0f, 0.0f);
    float2 hlast = make_float2(0.0f, 0.0f);
    const int gate = j >> 6;

    __syncthreads();

    for (int t = 0; t < SEQ; t++) {
        const int cur = t & 1;

        // gx = emb_proj[x[b,t]][j]  (issued early; consumed after matvec)
        float gx[8];
#pragma unroll
        for (int b = 0; b < 8; b++)
            gx[b] = g_emb_proj[xs[cur][b] * G4 + j];

        // matvec: acc lanes = (even-k partial, odd-k partial)
        float2 acc[8];
#pragma unroll
        for (int b = 0; b < 8; b++) acc[b] = make_float2(0.0f, 0.0f);
#pragma unroll
        for (int q = 0; q < 16; q++) {
#pragma unroll
            for (int b = 0; b < 8; b++) {
                float4 hv = *reinterpret_cast<const float4*>(&hS[b][q * 4]);
                float2 h01 = make_float2(hv.x, hv.y);
                float2 h23 = make_float2(hv.z, hv.w);
                acc[b] = ffma2(h01, wk[2 * q + 0], acc[b]);
                acc[b] = ffma2(h23, wk[2 * q + 1], acc[b]);
            }
        }

        // prefetch next-step token indices into the other buffer
        if (j < 8 && t + 1 < SEQ) xs[cur ^ 1][j] = x[(b0 + j) * SEQ + t + 1];

        // activation + store gates
#pragma unroll
        for (int b = 0; b < 8; b++) {
            float v = acc[b].x + acc[b].y + gx[b];
            float a = (gate == 2) ? tanh_(v) : sigmoid_(v);
            gS[b][j] = a;
        }
        __syncthreads();

        // update phase: thread (ku, pu) handles batches 2*pu, 2*pu+1
        {
            const int bA = 2 * pu, bB = 2 * pu + 1;
            float i0 = gS[bA][ku],       i1 = gS[bB][ku];
            float f0 = gS[bA][64 + ku],  f1 = gS[bB][64 + ku];
            float g0 = gS[bA][128 + ku], g1 = gS[bB][128 + ku];
            float o0 = gS[bA][192 + ku], o1 = gS[bB][192 + ku];
            c.x = fmaf(f0, c.x, i0 * g0);
            c.y = fmaf(f1, c.y, i1 * g1);
            hlast.x = o0 * tanh_(c.x);
            hlast.y = o1 * tanh_(c.y);
            hS[bA][ku] = hlast.x;
            hS[bB][ku] = hlast.y;
        }
        __syncthreads();
    }

    g_hfin[(b0 + 2 * pu)     * HID + ku] = hlast.x;
    g_hfin[(b0 + 2 * pu + 1) * HID + ku] = hlast.y;
}

// ---------------------------------------------------------------------------
// K3: out[b][c] = exp(h[b] . W_fc[c] + b_fc[c])  (unnormalized; logits are O(1))
// grid: ceil(50000/256)=196 CTAs x 256 threads; thread = city c; batch chunks of 16
// ---------------------------------------------------------------------------
__global__ void __launch_bounds__(256) k3_fc(
    const float* __restrict__ W_fc, const float* __restrict__ b_fc,
    float* __restrict__ out)
{
    __shared__ float hS[16][64];
    const int tid = threadIdx.x;
    const int c   = blockIdx.x * 256 + tid;
    const bool valid = (c < NUM_CITIES);

    float2 wk[32];
    float bias = 0.0f;
    if (valid) {
        const float2* wr = reinterpret_cast<const float2*>(W_fc + c * HID);
#pragma unroll
        for (int q = 0; q < 32; q++) wk[q] = wr[q];
        bias = b_fc[c];
    } else {
#pragma unroll
        for (int q = 0; q < 32; q++) wk[q] = make_float2(0.0f, 0.0f);
    }

    for (int bc = 0; bc < BATCH; bc += 16) {
        __syncthreads();
#pragma unroll
        for (int q = 0; q < 4; q++) {
            int idx = tid + q * 256;          // 0..1023 covers 16x64
            hS[idx >> 6][idx & 63] = g_hfin[bc * HID + idx];
        }
        __syncthreads();

        float2 acc[16];
#pragma unroll
        for (int b = 0; b < 16; b++) acc[b] = make_float2(0.0f, 0.0f);
#pragma unroll 4
        for (int q = 0; q < 16; q++) {
#pragma unroll
            for (int b = 0; b < 16; b++) {
                float4 hv = *reinterpret_cast<const float4*>(&hS[b][q * 4]);
                float2 h01 = make_float2(hv.x, hv.y);
                float2 h23 = make_float2(hv.z, hv.w);
                acc[b] = ffma2(h01, wk[2 * q + 0], acc[b]);
                acc[b] = ffma2(h23, wk[2 * q + 1], acc[b]);
            }
        }

        if (valid) {
#pragma unroll
            for (int b = 0; b < 16; b++) {
                float l = acc[b].x + acc[b].y + bias;
                float e = fast_ex2(l * 1.4426950408889634f);   // exp(l)
                out[(size_t)(bc + b) * NUM_CITIES + c] = e;
            }
        }
    }
}

// ---------------------------------------------------------------------------
// K4: per-row softmax normalization. One CTA per batch row; whole 200KB row
// staged in dynamic smem so d_out is read exactly once and written once.
// ---------------------------------------------------------------------------
__global__ void __launch_bounds__(512) k4_softmax(float* __restrict__ out)
{
    extern __shared__ float row[];
    __shared__ float wsum[16];
    const int b   = blockIdx.x;
    const int tid = threadIdx.x;
    float4* dst = reinterpret_cast<float4*>(out + (size_t)b * NUM_CITIES);
    float4* r4  = reinterpret_cast<float4*>(row);

    float s = 0.0f;
    for (int i = tid; i < NUM_CITIES / 4; i += 512) {
        float4 v = dst[i];
        r4[i] = v;
        s += (v.x + v.y) + (v.z + v.w);
    }
#pragma unroll
    for (int off = 16; off; off >>= 1)
        s += __shfl_xor_sync(0xffffffffu, s, off);
    if ((tid & 31) == 0) wsum[tid >> 5] = s;
    __syncthreads();
    if (tid == 0) {
        float tot = 0.0f;
#pragma unroll
        for (int w = 0; w < 16; w++) tot += wsum[w];
        wsum[0] = 1.0f / tot;
    }
    __syncthreads();
    const float inv = wsum[0];

    for (int i = tid; i < NUM_CITIES / 4; i += 512) {
        float4 v = r4[i];
        v.x *= inv; v.y *= inv; v.z *= inv; v.w *= inv;
        dst[i] = v;
    }
}

// ---------------------------------------------------------------------------
extern "C" void kernel_launch(void* const* d_in, const int* in_sizes, int n_in,
                              void* d_out, int out_size)
{
    (void)in_sizes; (void)n_in; (void)out_size;
    const int*   x    = (const int*)  d_in[0];
    const float* emb  = (const float*)d_in[1];
    const float* W_ih = (const float*)d_in[2];
    const float* W_hh = (const float*)d_in[3];
    const float* b_ih = (const float*)d_in[4];
    const float* b_hh = (const float*)d_in[5];
    const float* W_fc = (const float*)d_in[6];
    const float* b_fc = (const float*)d_in[7];
    float* out = (float*)d_out;

    cudaFuncSetAttribute(k4_softmax, cudaFuncAttributeMaxDynamicSharedMemorySize,
                         NUM_CITIES * (int)sizeof(float));

    k1_embproj<<<NUM_CITIES / 20, 256>>>(emb, W_ih, b_ih, b_hh);
    k2_lstm<<<BATCH / 8, 256>>>(x, W_hh);
    k3_fc<<<(NUM_CITIES + 255) / 256, 256>>>(W_fc, b_fc, out);
    k4_softmax<<<BATCH, 512, NUM_CITIES * (int)sizeof(float)>>>(out);
}

// round 3
// speedup vs baseline: 1.1015x; 1.1015x over previous
#include <cuda_runtime.h>
#include <cstdint>

typedef unsigned long long u64;
typedef unsigned int u32;

#define NUM_CITIES 50000
#define EMB 50
#define HID 64
#define G4 256          // 4 * HID
#define BATCH 1024
#define SEQ 512
#define K3_CTAS 196     // ceil(50000/256)

// Scratch (no allocation allowed -> device globals)
__device__ float g_emb_proj[NUM_CITIES * G4];     // emb @ W_ih^T + bias, 51.2MB
__device__ float g_hfin[BATCH * HID];             // final hidden state
__device__ float g_partial[K3_CTAS * BATCH];      // per-CTA row partial sums
__device__ float g_rowinv[BATCH];                 // 1/rowsum

// ---------------------------------------------------------------------------
// helpers
// ---------------------------------------------------------------------------
__device__ __forceinline__ float fast_ex2(float x) {
    float r; asm("ex2.approx.f32 %0, %1;" : "=f"(r) : "f"(x)); return r;
}
__device__ __forceinline__ float fast_rcp(float x) {
    float r; asm("rcp.approx.f32 %0, %1;" : "=f"(r) : "f"(x)); return r;
}
__device__ __forceinline__ float sigmoid_(float x) {
    return fast_rcp(1.0f + fast_ex2(-1.4426950408889634f * x));
}
__device__ __forceinline__ float tanh_(float x) {
    return fmaf(2.0f, sigmoid_(2.0f * x), -1.0f);
}
__device__ __forceinline__ u32 sptr(const void* p) {
    return (u32)__cvta_generic_to_shared(p);
}
__device__ __forceinline__ void unpack2(u64 v, float& lo, float& hi) {
    asm("mov.b64 {%0,%1}, %2;" : "=f"(lo), "=f"(hi) : "l"(v));
}

// ---------------------------------------------------------------------------
// K1: emb_proj[r][j] = sum_k emb[r][k] * W_ih[j][k] + (b_ih[j]+b_hh[j])
// ---------------------------------------------------------------------------
__global__ void __launch_bounds__(256) k1_embproj(
    const float* __restrict__ emb, const float* __restrict__ W_ih,
    const float* __restrict__ b_ih, const float* __restrict__ b_hh)
{
    __shared__ float es[20][52];
    const int j  = threadIdx.x;
    const int r0 = blockIdx.x * 20;

    float w[52];
#pragma unroll
    for (int k = 0; k < 50; k++) w[k] = W_ih[j * 50 + k];
    w[50] = 0.0f; w[51] = 0.0f;
    const float bias = b_ih[j] + b_hh[j];

    for (int idx = j; idx < 20 * 50; idx += 256)
        es[idx / 50][idx % 50] = emb[(r0 + idx / 50) * 50 + (idx % 50)];
    if (j < 40) es[j >> 1][50 + (j & 1)] = 0.0f;
    __syncthreads();

#pragma unroll 4
    for (int r = 0; r < 20; r++) {
        float acc = bias;
#pragma unroll
        for (int q = 0; q < 13; q++) {
            float4 e4 = *reinterpret_cast<const float4*>(&es[r][q * 4]);
            acc = fmaf(e4.x, w[4 * q + 0], acc);
            acc = fmaf(e4.y, w[4 * q + 1], acc);
            acc = fmaf(e4.z, w[4 * q + 2], acc);
            acc = fmaf(e4.w, w[4 * q + 3], acc);
        }
        g_emb_proj[(r0 + r) * G4 + j] = acc;
    }
}

// ---------------------------------------------------------------------------
// K2: LSTM recurrence. 128 CTAs x 512 threads, 8 batch rows per CTA.
// tid & 255  = gate column j  (gate order: [0,64)=i [64,128)=f [128,192)=g [192,256)=o)
// tid >> 8   = batch half (each thread does 4 batches)
// Update phase: tid = b*64 + k over all 512 (b,k) pairs.
// ---------------------------------------------------------------------------
__global__ void __launch_bounds__(512) k2_lstm(
    const int* __restrict__ x, const float* __restrict__ W_hh)
{
    __shared__ __align__(16) float hS[8][64];
    __shared__ float gS[8][256];
    __shared__ int   xs[2][8];

    const int tid = threadIdx.x;
    const int j   = tid & 255;
    const int bh  = (tid >> 8) * 4;    // batch base: 0 or 4
    const int b0  = blockIdx.x * 8;
    const int gate = j >> 6;

    // W_hh row j as 32 packed f32x2 (k pairs), via 16 LDG.128
    u64 wk[32];
    {
        const ulonglong2* wr = reinterpret_cast<const ulonglong2*>(W_hh + j * HID);
#pragma unroll
        for (int q = 0; q < 16; q++) { ulonglong2 t = wr[q]; wk[2*q] = t.x; wk[2*q+1] = t.y; }
    }

    hS[tid >> 6][tid & 63] = 0.0f;
    if (tid < 8) xs[0][tid] = x[(b0 + tid) * SEQ];

    const int ub = tid >> 6;   // update batch
    const int uk = tid & 63;   // update column
    float c  = 0.0f;
    float hl = 0.0f;

    const u32 hbase = sptr(hS) + (u32)bh * 256u;  // this half's batch rows

    __syncthreads();

    for (int t = 0; t < SEQ; t++) {
        const int cur = t & 1;

        // gather gx early
        float gx[4];
#pragma unroll
        for (int b = 0; b < 4; b++)
            gx[b] = __ldg(&g_emb_proj[xs[cur][bh + b] * G4 + j]);

        // matvec: acc lanes = (even-k partial, odd-k partial)
        u64 acc0 = 0, acc1 = 0, acc2 = 0, acc3 = 0;
#pragma unroll
        for (int q = 0; q < 16; q++) {
            u64 a01, a23, b01, b23, c01, c23, d01, d23;
            asm volatile("ld.shared.v2.u64 {%0,%1}, [%2];"
                         : "=l"(a01), "=l"(a23) : "r"(hbase + 0u * 256u + (u32)q * 16u));
            asm volatile("ld.shared.v2.u64 {%0,%1}, [%2];"
                         : "=l"(b01), "=l"(b23) : "r"(hbase + 1u * 256u + (u32)q * 16u));
            asm volatile("ld.shared.v2.u64 {%0,%1}, [%2];"
                         : "=l"(c01), "=l"(c23) : "r"(hbase + 2u * 256u + (u32)q * 16u));
            asm volatile("ld.shared.v2.u64 {%0,%1}, [%2];"
                         : "=l"(d01), "=l"(d23) : "r"(hbase + 3u * 256u + (u32)q * 16u));
            asm volatile("fma.rn.f32x2 %0, %1, %2, %0;" : "+l"(acc0) : "l"(a01), "l"(wk[2*q]));
            asm volatile("fma.rn.f32x2 %0, %1, %2, %0;" : "+l"(acc1) : "l"(b01), "l"(wk[2*q]));
            asm volatile("fma.rn.f32x2 %0, %1, %2, %0;" : "+l"(acc2) : "l"(c01), "l"(wk[2*q]));
            asm volatile("fma.rn.f32x2 %0, %1, %2, %0;" : "+l"(acc3) : "l"(d01), "l"(wk[2*q]));
            asm volatile("fma.rn.f32x2 %0, %1, %2, %0;" : "+l"(acc0) : "l"(a23), "l"(wk[2*q+1]));
            asm volatile("fma.rn.f32x2 %0, %1, %2, %0;" : "+l"(acc1) : "l"(b23), "l"(wk[2*q+1]));
            asm volatile("fma.rn.f32x2 %0, %1, %2, %0;" : "+l"(acc2) : "l"(c23), "l"(wk[2*q+1]));
            asm volatile("fma.rn.f32x2 %0, %1, %2, %0;" : "+l"(acc3) : "l"(d23), "l"(wk[2*q+1]));
        }

        // prefetch next token indices
        if (tid < 8 && t + 1 < SEQ) xs[cur ^ 1][tid] = x[(b0 + tid) * SEQ + t + 1];

        // activation + store gates
        {
            float lo, hi, v;
            unpack2(acc0, lo, hi); v = lo + hi + gx[0];
            gS[bh + 0][j] = (gate == 2) ? tanh_(v) : sigmoid_(v);
            unpack2(acc1, lo, hi); v = lo + hi + gx[1];
            gS[bh + 1][j] = (gate == 2) ? tanh_(v) : sigmoid_(v);
            unpack2(acc2, lo, hi); v = lo + hi + gx[2];
            gS[bh + 2][j] = (gate == 2) ? tanh_(v) : sigmoid_(v);
            unpack2(acc3, lo, hi); v = lo + hi + gx[3];
            gS[bh + 3][j] = (gate == 2) ? tanh_(v) : sigmoid_(v);
        }
        __syncthreads();

        // update: one thread per (batch, column)
        {
            float i_ = gS[ub][uk];
            float f_ = gS[ub][64 + uk];
            float g_ = gS[ub][128 + uk];
            float o_ = gS[ub][192 + uk];
            c  = fmaf(f_, c, i_ * g_);
            hl = o_ * tanh_(c);
            hS[ub][uk] = hl;
        }
        __syncthreads();
    }

    g_hfin[(b0 + ub) * HID + uk] = hl;
}

// ---------------------------------------------------------------------------
// K3: out[b][c] = exp(h[b].W_fc[c] + b_fc[c]); also per-CTA row partial sums
// 196 CTAs x 256 threads; thread = city c; batch chunks of 16
// ---------------------------------------------------------------------------
__global__ void __launch_bounds__(256) k3_fc(
    const float* __restrict__ W_fc, const float* __restrict__ b_fc,
    float* __restrict__ out)
{
    __shared__ __align__(16) float hS[16][64];
    __shared__ float ws[8][16];

    const int tid  = threadIdx.x;
    const int wid  = tid >> 5;
    const int lane = tid & 31;
    const int c    = blockIdx.x * 256 + tid;
    const bool valid = (c < NUM_CITIES);

    u64 wk[32];
    float bias = 0.0f;
    if (valid) {
        const ulonglong2* wr = reinterpret_cast<const ulonglong2*>(W_fc + c * HID);
#pragma unroll
        for (int q = 0; q < 16; q++) { ulonglong2 t = wr[q]; wk[2*q] = t.x; wk[2*q+1] = t.y; }
        bias = b_fc[c];
    } else {
#pragma unroll
        for (int q = 0; q < 32; q++) wk[q] = 0ull;
    }

    const u32 hbase = sptr(hS);

    for (int bc = 0; bc < BATCH; bc += 16) {
        __syncthreads();   // hS/ws safe to overwrite
        reinterpret_cast<float4*>(hS)[tid] =
            reinterpret_cast<const float4*>(g_hfin + bc * HID)[tid];
        __syncthreads();

        u64 acc[16];
#pragma unroll
        for (int b = 0; b < 16; b++) acc[b] = 0ull;

#pragma unroll
        for (int q = 0; q < 16; q++) {
#pragma unroll
            for (int b = 0; b < 16; b++) {
                u64 h01, h23;
                asm volatile("ld.shared.v2.u64 {%0,%1}, [%2];"
                             : "=l"(h01), "=l"(h23)
                             : "r"(hbase + (u32)b * 256u + (u32)q * 16u));
                asm volatile("fma.rn.f32x2 %0, %1, %2, %0;" : "+l"(acc[b]) : "l"(h01), "l"(wk[2*q]));
                asm volatile("fma.rn.f32x2 %0, %1, %2, %0;" : "+l"(acc[b]) : "l"(h23), "l"(wk[2*q+1]));
            }
        }

#pragma unroll
        for (int b = 0; b < 16; b++) {
            float lo, hi;
            unpack2(acc[b], lo, hi);
            float l = lo + hi + bias;
            float e = fast_ex2(l * 1.4426950408889634f);
            float ev = valid ? e : 0.0f;
            if (valid) __stcs(&out[(size_t)(bc + b) * NUM_CITIES + c], e);
            // warp reduction for row sum
            ev += __shfl_xor_sync(0xffffffffu, ev, 16);
            ev += __shfl_xor_sync(0xffffffffu, ev, 8);
            ev += __shfl_xor_sync(0xffffffffu, ev, 4);
            ev += __shfl_xor_sync(0xffffffffu, ev, 2);
            ev += __shfl_xor_sync(0xffffffffu, ev, 1);
            if (lane == 0) ws[wid][b] = ev;
        }
        __syncthreads();

        if (tid < 16) {
            float s = 0.0f;
#pragma unroll
            for (int w = 0; w < 8; w++) s += ws[w][tid];
            g_partial[blockIdx.x * BATCH + bc + tid] = s;
        }
    }
}

// ---------------------------------------------------------------------------
// K3c: exact row-sum inverses (deterministic reduction over 196 partials)
// ---------------------------------------------------------------------------
__global__ void __launch_bounds__(128) k3c_inv()
{
    const int b = blockIdx.x * 128 + threadIdx.x;   // grid 8 x 128 = 1024
    float s = 0.0f;
#pragma unroll 4
    for (int cta = 0; cta < K3_CTAS; cta++)
        s += g_partial[cta * BATCH + b];
    g_rowinv[b] = 1.0f / s;
}

// ---------------------------------------------------------------------------
// K4: pure streaming scale. One float4 per thread, full occupancy.
// ---------------------------------------------------------------------------
__global__ void __launch_bounds__(256) k4_scale(float4* __restrict__ out4)
{
    const int i = blockIdx.x * 256 + threadIdx.x;    // < 12,800,000
    const int b = i / (NUM_CITIES / 4);
    const float inv = g_rowinv[b];
    float4 v = __ldcs(&out4[i]);
    v.x *= inv; v.y *= inv; v.z *= inv; v.w *= inv;
    __stcs(&out4[i], v);
}

// ---------------------------------------------------------------------------
extern "C" void kernel_launch(void* const* d_in, const int* in_sizes, int n_in,
                              void* d_out, int out_size)
{
    (void)in_sizes; (void)n_in; (void)out_size;
    const int*   x    = (const int*)  d_in[0];
    const float* emb  = (const float*)d_in[1];
    const float* W_ih = (const float*)d_in[2];
    const float* W_hh = (const float*)d_in[3];
    const float* b_ih = (const float*)d_in[4];
    const float* b_hh = (const float*)d_in[5];
    const float* W_fc = (const float*)d_in[6];
    const float* b_fc = (const float*)d_in[7];
    float* out = (float*)d_out;

    k1_embproj<<<NUM_CITIES / 20, 256>>>(emb, W_ih, b_ih, b_hh);
    k2_lstm<<<BATCH / 8, 512>>>(x, W_hh);
    k3_fc<<<K3_CTAS, 256>>>(W_fc, b_fc, out);
    k3c_inv<<<8, 128>>>();
    k4_scale<<<(BATCH * NUM_CITIES / 4) / 256, 256>>>((float4*)out);
}